// round 5
// baseline (speedup 1.0000x reference)
#include <cuda_runtime.h>
#include <math.h>

// Tile geometry: 64x32 outputs per block, halo 4 on input.
#define TDX 64
#define TDY 32
#define IW_W 72
#define IW_H 40
#define BW_W 70
#define BW_H 38
#define MW_W 68
#define MW_H 36
#define SW_W 66
#define SW_H 34
#define NTHREADS 512

// MODE: 0 = interior blocks (no bounds checks on fast path), 1 = border ring,
//       2 = all blocks (single-launch fallback for tiny grids)
template<int MODE>
__global__ __launch_bounds__(NTHREADS)
void canny_fused_kernel(const float* __restrict__ img,
                        const float* __restrict__ gauss_w,   // (C,1,3,3)
                        const float* __restrict__ sobel_x_w, // (C,1,3,3)
                        const float* __restrict__ sobel_y_w, // (C,1,3,3)
                        const float* __restrict__ dir_w,     // (8,1,3,3)
                        const float* __restrict__ nms_w,     // (1,8,3,3)
                        float* __restrict__ out,
                        int B, int C, int H, int W, int nbx, int nby)
{
    __shared__ float simg [IW_W * IW_H];   // 2880
    __shared__ float sblur[BW_W * BW_H];   // 2660
    __shared__ float sgx  [MW_W * MW_H];   // 2448  fast: magnitude
    __shared__ float buf2 [MW_W * MW_H];   // 2448  fast: sS (needs 2244); generic: sgy
    __shared__ float kcomp[81];            // composed kernels: kcomp[off*9+tap]
    __shared__ float kgf[9], ksxf[9], ksyf[9];
    __shared__ int   sbad;

    float* const sS  = buf2;
    float* const sgy = buf2;

    const int tid = threadIdx.x;
    const int b   = blockIdx.z;

    int bx, by;
    if (MODE == 0) { bx = blockIdx.x + 1; by = blockIdx.y + 1; }
    else if (MODE == 2) { bx = blockIdx.x; by = blockIdx.y; }
    else {
        int idx = blockIdx.x;
        if (idx < nbx)            { bx = idx;            by = 0; }
        else if (idx < 2 * nbx)   { bx = idx - nbx;      by = nby - 1; }
        else { int rem = idx - 2 * nbx; by = 1 + (rem >> 1); bx = (rem & 1) * (nbx - 1); }
    }
    const int x0 = bx * TDX;
    const int y0 = by * TDY;
    const float invC = 1.0f / (float)C;
    const bool NOCHK = (MODE == 0);

    // ---- phase A: stage weights, compose kcomp, init flag ----
    if (tid < 81) {
        int off = tid / 9, t = tid % 9;
        float acc = 0.f;
        #pragma unroll
        for (int d = 0; d < 8; d++)
            acc = fmaf(__ldg(&nms_w[d * 9 + off]), __ldg(&dir_w[d * 9 + t]), acc);
        kcomp[tid] = acc;
    }
    if (tid < 9) {
        kgf [tid] = __ldg(&gauss_w[tid]);
        ksxf[tid] = __ldg(&sobel_x_w[tid]);
        ksyf[tid] = __ldg(&sobel_y_w[tid]);
    }
    if (tid == 0) sbad = 0;
    __syncthreads();

    // ---- phase B: fast-path validity checks ----
    for (int i = tid; i < 27 * (C - 1); i += NTHREADS) {
        int ch = 1 + i / 27, j = i % 27, arr = j / 9, t = j % 9;
        const float* base = (arr == 0) ? gauss_w : (arr == 1) ? sobel_x_w : sobel_y_w;
        if (__float_as_uint(__ldg(&base[ch * 9 + t])) != __float_as_uint(__ldg(&base[t])))
            atomicOr(&sbad, 1);
    }
    if (tid == 0) {
        int u = 0;
        #pragma unroll
        for (int t = 0; t < 9; t++) if (kcomp[4 * 9 + t] != 0.f) u = 1;
        for (int off = 0; off < 9; off++) {
            if (off == 4) continue;
            #pragma unroll
            for (int t = 0; t < 9; t++) if (kcomp[off * 9 + t] != kcomp[t]) u = 1;
        }
        if (u) atomicOr(&sbad, 1);
    }
    __syncthreads();
    const bool fast = (sbad == 0);

    if (fast) {
        // ================= FAST PATH (shared weights, uniform NMS) ==========
        // stage 0: channel-summed image tile, halo 4
        const size_t plane = (size_t)H * W;
        for (int i = tid; i < IW_W * IW_H; i += NTHREADS) {
            int r = i / IW_W, c = i % IW_W;
            float v = 0.f;
            if (NOCHK) {
                size_t base = (size_t)b * C * plane + (size_t)(y0 - 4 + r) * W + (x0 - 4 + c);
                if (C == 3) {
                    float v0 = __ldg(&img[base]);
                    float v1 = __ldg(&img[base + plane]);
                    float v2 = __ldg(&img[base + 2 * plane]);
                    v = v0 + v1 + v2;
                } else {
                    for (int ch = 0; ch < C; ch++) v += __ldg(&img[base + (size_t)ch * plane]);
                }
            } else {
                int gy = y0 - 4 + r, gx = x0 - 4 + c;
                if (gy >= 0 && gy < H && gx >= 0 && gx < W) {
                    size_t base = (size_t)b * C * plane + (size_t)gy * W + gx;
                    if (C == 3) {
                        float v0 = __ldg(&img[base]);
                        float v1 = __ldg(&img[base + plane]);
                        float v2 = __ldg(&img[base + 2 * plane]);
                        v = v0 + v1 + v2;
                    } else {
                        for (int ch = 0; ch < C; ch++) v += __ldg(&img[base + (size_t)ch * plane]);
                    }
                }
            }
            simg[i] = v;
        }
        __syncthreads();

        // stage 1: gaussian blur (strips of 2): 35 strips x 38 rows = 1330 units
        for (int u = tid; u < 35 * BW_H; u += NTHREADS) {
            int row = u / 35, cs = (u % 35) * 2;
            float a[3][4];
            #pragma unroll
            for (int dr = 0; dr < 3; dr++)
                #pragma unroll
                for (int dc = 0; dc < 4; dc++)
                    a[dr][dc] = simg[(row + dr) * IW_W + cs + dc];
            float o0 = 0.f, o1 = 0.f;
            #pragma unroll
            for (int dr = 0; dr < 3; dr++)
                #pragma unroll
                for (int dc = 0; dc < 3; dc++) {
                    float w = kgf[dr * 3 + dc];
                    o0 = fmaf(w, a[dr][dc],     o0);
                    o1 = fmaf(w, a[dr][dc + 1], o1);
                }
            if (!NOCHK) {
                int gy = y0 - 3 + row, gx = x0 - 3 + cs;
                bool iny = (gy >= 0 && gy < H);
                if (!(iny && gx     >= 0 && gx     < W)) o0 = 0.f;
                if (!(iny && gx + 1 >= 0 && gx + 1 < W)) o1 = 0.f;
            }
            sblur[row * BW_W + cs]     = o0;
            sblur[row * BW_W + cs + 1] = o1;
        }
        __syncthreads();

        // stage 2: sobel + magnitude (strips of 4): 17 strips x 36 rows = 612
        for (int u = tid; u < 17 * MW_H; u += NTHREADS) {
            int row = u / 17, cs = (u % 17) * 4;
            float bv[3][6];
            #pragma unroll
            for (int dr = 0; dr < 3; dr++)
                #pragma unroll
                for (int dc = 0; dc < 6; dc++)
                    bv[dr][dc] = sblur[(row + dr) * BW_W + cs + dc];
            #pragma unroll
            for (int k = 0; k < 4; k++) {
                float ax = 0.f, ay = 0.f;
                #pragma unroll
                for (int dr = 0; dr < 3; dr++)
                    #pragma unroll
                    for (int dc = 0; dc < 3; dc++) {
                        float t = bv[dr][dc + k];
                        ax = fmaf(ksxf[dr * 3 + dc], t, ax);
                        ay = fmaf(ksyf[dr * 3 + dc], t, ay);
                    }
                ax *= invC; ay *= invC;
                float m = sqrtf(ax * ax + ay * ay);
                if (!NOCHK) {
                    int gy = y0 - 2 + row, gx = x0 - 2 + cs + k;
                    if (!(gy >= 0 && gy < H && gx >= 0 && gx < W)) m = 0.f;
                }
                sgx[row * MW_W + cs + k] = m;
            }
        }
        __syncthreads();

        // stage 3: S = conv(mag, Ksum) (strips of 2): 33 strips x 34 rows = 1122
        for (int u = tid; u < 33 * SW_H; u += NTHREADS) {
            int row = u / 33, cs = (u % 33) * 2;
            float m[3][4];
            #pragma unroll
            for (int dr = 0; dr < 3; dr++)
                #pragma unroll
                for (int dc = 0; dc < 4; dc++)
                    m[dr][dc] = sgx[(row + dr) * MW_W + cs + dc];
            float s0 = 0.f, s1 = 0.f;
            #pragma unroll
            for (int dr = 0; dr < 3; dr++)
                #pragma unroll
                for (int dc = 0; dc < 3; dc++) {
                    float w = kcomp[dr * 3 + dc];
                    s0 = fmaf(w, m[dr][dc],     s0);
                    s1 = fmaf(w, m[dr][dc + 1], s1);
                }
            if (!NOCHK) {
                int gy = y0 - 1 + row, gx = x0 - 1 + cs;
                bool iny = (gy >= 0 && gy < H);
                if (!(iny && gx     >= 0 && gx     < W)) s0 = 0.f;
                if (!(iny && gx + 1 >= 0 && gx + 1 < W)) s1 = 0.f;
            }
            sS[row * SW_W + cs]     = s0;
            sS[row * SW_W + cs + 1] = s1;
        }
        __syncthreads();

        // stage 4: 8-neighbor sum of S; exactly 512 units of 4; float4 store
        {
            int row = tid / 16, cs = (tid % 16) * 4;
            float s[3][6];
            #pragma unroll
            for (int dr = 0; dr < 3; dr++)
                #pragma unroll
                for (int dc = 0; dc < 6; dc++)
                    s[dr][dc] = sS[(row + dr) * SW_W + cs + dc];
            float o[4];
            #pragma unroll
            for (int k = 0; k < 4; k++) {
                float acc = 0.f;
                #pragma unroll
                for (int dr = 0; dr < 3; dr++)
                    #pragma unroll
                    for (int dc = 0; dc < 3; dc++) {
                        if (dr == 1 && dc == 1) continue;   // exclude center exactly
                        acc += s[dr][dc + k];
                    }
                o[k] = acc;
            }
            size_t oidx = ((size_t)b * H + (y0 + row)) * W + x0 + cs;
            *reinterpret_cast<float4*>(&out[oidx]) = make_float4(o[0], o[1], o[2], o[3]);
        }
    } else {
        // ================= GENERIC PATH (always bounds-checked) =============
        for (int i = tid; i < MW_W * MW_H; i += NTHREADS) { sgx[i] = 0.f; sgy[i] = 0.f; }
        __syncthreads();

        for (int ch = 0; ch < C; ch++) {
            for (int i = tid; i < IW_W * IW_H; i += NTHREADS) {
                int r = i / IW_W, c = i % IW_W;
                int gy = y0 - 4 + r, gx = x0 - 4 + c;
                float v = 0.f;
                if (gy >= 0 && gy < H && gx >= 0 && gx < W)
                    v = img[(((size_t)b * C + ch) * H + gy) * W + gx];
                simg[i] = v;
            }
            float wg[9], wx[9], wy[9];
            #pragma unroll
            for (int t = 0; t < 9; t++) {
                wg[t] = __ldg(&gauss_w  [ch * 9 + t]);
                wx[t] = __ldg(&sobel_x_w[ch * 9 + t]);
                wy[t] = __ldg(&sobel_y_w[ch * 9 + t]);
            }
            __syncthreads();
            for (int i = tid; i < BW_W * BW_H; i += NTHREADS) {
                int row = i / BW_W, c = i % BW_W;
                int gy = y0 - 3 + row, gx = x0 - 3 + c;
                float v = 0.f;
                if (gy >= 0 && gy < H && gx >= 0 && gx < W) {
                    #pragma unroll
                    for (int dr = 0; dr < 3; dr++)
                        #pragma unroll
                        for (int dc = 0; dc < 3; dc++)
                            v = fmaf(wg[dr * 3 + dc], simg[(row + dr) * IW_W + c + dc], v);
                }
                sblur[i] = v;
            }
            __syncthreads();
            for (int i = tid; i < MW_W * MW_H; i += NTHREADS) {
                int row = i / MW_W, c = i % MW_W;
                float ax = 0.f, ay = 0.f;
                #pragma unroll
                for (int dr = 0; dr < 3; dr++)
                    #pragma unroll
                    for (int dc = 0; dc < 3; dc++) {
                        float t = sblur[(row + dr) * BW_W + c + dc];
                        ax = fmaf(wx[dr * 3 + dc], t, ax);
                        ay = fmaf(wy[dr * 3 + dc], t, ay);
                    }
                sgx[i] += ax;
                sgy[i] += ay;
            }
            __syncthreads();
        }
        // magnitude in place into sgx, zeroed outside grid
        for (int i = tid; i < MW_W * MW_H; i += NTHREADS) {
            int row = i / MW_W, c = i % MW_W;
            int gy = y0 - 2 + row, gx = x0 - 2 + c;
            float m = 0.f;
            if (gy >= 0 && gy < H && gx >= 0 && gx < W) {
                float gxx = sgx[i] * invC, gyy = sgy[i] * invC;
                m = sqrtf(gxx * gxx + gyy * gyy);
            }
            sgx[i] = m;
        }
        __syncthreads();
        // directional + nms via per-offset composed kernels
        for (int i = tid; i < TDX * TDY; i += NTHREADS) {
            int r = i / TDX, c = i % TDX;
            int y = y0 + r, x = x0 + c;
            float acc = 0.f;
            #pragma unroll
            for (int oi = 0; oi < 3; oi++)
                #pragma unroll
                for (int oj = 0; oj < 3; oj++) {
                    int p = y + oi - 1, q = x + oj - 1;
                    if (p < 0 || p >= H || q < 0 || q >= W) continue;
                    float s = 0.f;
                    #pragma unroll
                    for (int dr = 0; dr < 3; dr++)
                        #pragma unroll
                        for (int dc = 0; dc < 3; dc++)
                            s = fmaf(kcomp[(oi * 3 + oj) * 9 + dr * 3 + dc],
                                     sgx[(r + oi + dr) * MW_W + c + oj + dc], s);
                    acc += s;
                }
            out[((size_t)b * H + y) * W + x] = acc;
        }
    }
}

extern "C" void kernel_launch(void* const* d_in, const int* in_sizes, int n_in,
                              void* d_out, int out_size)
{
    const float* img       = (const float*)d_in[0];
    const float* gauss_w   = (const float*)d_in[1];
    const float* sobel_x_w = (const float*)d_in[2];
    const float* sobel_y_w = (const float*)d_in[3];
    const float* dir_w     = (const float*)d_in[4];
    const float* nms_w     = (const float*)d_in[5];
    float* out = (float*)d_out;

    const int H = 512, W = 512;
    const int C = in_sizes[1] / 9;                 // (C,1,3,3) -> C
    const int B = in_sizes[0] / (C * H * W);
    const int nbx = W / TDX, nby = H / TDY;        // 8 x 16

    if (nbx > 2 && nby > 2) {
        dim3 gi(nbx - 2, nby - 2, B);
        canny_fused_kernel<0><<<gi, NTHREADS>>>(img, gauss_w, sobel_x_w, sobel_y_w,
                                                dir_w, nms_w, out, B, C, H, W, nbx, nby);
        dim3 gb(2 * nbx + 2 * (nby - 2), 1, B);
        canny_fused_kernel<1><<<gb, NTHREADS>>>(img, gauss_w, sobel_x_w, sobel_y_w,
                                                dir_w, nms_w, out, B, C, H, W, nbx, nby);
    } else {
        dim3 g(nbx, nby, B);
        canny_fused_kernel<2><<<g, NTHREADS>>>(img, gauss_w, sobel_x_w, sobel_y_w,
                                               dir_w, nms_w, out, B, C, H, W, nbx, nby);
    }
}

// round 10
// speedup vs baseline: 1.7244x; 1.7244x over previous
#include <cuda_runtime.h>
#include <math.h>

// Tile geometry: 64x32 outputs per block, halo 4 on input.
#define TDX 64
#define TDY 32
#define IW_W 72
#define IW_H 40
#define BW_W 70
#define BW_H 38
#define MW_W 68
#define MW_H 36
#define SW_W 66
#define SW_H 34
#define NTHREADS 512

// ===========================================================================
// FAST kernel: valid when gaussian/sobel weights are channel-replicated and
// NMS weights are uniform-with-zero-center. Verified per block (cheap, L2-hot);
// early-exits otherwise (the generic kernel then produces the output).
// __launch_bounds__(512,3): cap regs at 42 -> 3 blocks/SM (75% occupancy).
// ===========================================================================
__global__ __launch_bounds__(NTHREADS, 3)
void canny_fast_kernel(const float* __restrict__ img,
                       const float* __restrict__ gauss_w,   // (C,1,3,3)
                       const float* __restrict__ sobel_x_w, // (C,1,3,3)
                       const float* __restrict__ sobel_y_w, // (C,1,3,3)
                       const float* __restrict__ dir_w,     // (8,1,3,3)
                       const float* __restrict__ nms_w,     // (1,8,3,3)
                       float* __restrict__ out,
                       int B, int C, int H, int W)
{
    __shared__ float simg [IW_W * IW_H];   // 2880
    __shared__ float sblur[BW_W * BW_H];   // 2660
    __shared__ float smag [MW_W * MW_H];   // 2448
    __shared__ float sS   [SW_W * SW_H];   // 2244
    __shared__ float ksum [9];             // sum_d dir_w[d] (uniform NMS case)
    __shared__ float kgf[9], ksxf[9], ksyf[9];
    __shared__ int   sbad;

    const int tid = threadIdx.x;
    const int b   = blockIdx.z;
    const int x0  = blockIdx.x * TDX;
    const int y0  = blockIdx.y * TDY;
    const float invC = 1.0f / (float)C;

    // ---- validity check + weight staging ----
    if (tid == 0) sbad = 0;
    if (tid < 9) {
        kgf [tid] = __ldg(&gauss_w[tid]);
        ksxf[tid] = __ldg(&sobel_x_w[tid]);
        ksyf[tid] = __ldg(&sobel_y_w[tid]);
        float acc = 0.f;
        #pragma unroll
        for (int d = 0; d < 8; d++)
            acc = fmaf(__ldg(&nms_w[d * 9]), __ldg(&dir_w[d * 9 + tid]), acc);
        ksum[tid] = acc;   // valid only if NMS uniform; checked below
    }
    __syncthreads();

    // channel replication of gauss/sobel (bitwise)
    for (int i = tid; i < 27 * (C - 1); i += NTHREADS) {
        int ch = 1 + i / 27, j = i % 27, arr = j / 9, t = j % 9;
        const float* base = (arr == 0) ? gauss_w : (arr == 1) ? sobel_x_w : sobel_y_w;
        if (__float_as_uint(__ldg(&base[ch * 9 + t])) != __float_as_uint(__ldg(&base[t])))
            atomicOr(&sbad, 1);
    }
    // NMS uniformity: for every d, nms_w[d*9+off] == nms_w[d*9+0] for off!=4,
    // and nms_w[d*9+4] == 0. Under this condition the composed per-offset
    // kernels collapse to (off-center: conv with ksum; center: zero).
    if (tid < 8) {
        float n0 = __ldg(&nms_w[tid * 9]);
        #pragma unroll
        for (int off = 0; off < 9; off++) {
            float nv = __ldg(&nms_w[tid * 9 + off]);
            if (off == 4) { if (nv != 0.f) atomicOr(&sbad, 1); }
            else          { if (__float_as_uint(nv) != __float_as_uint(n0)) atomicOr(&sbad, 1); }
        }
    }
    __syncthreads();
    if (sbad) return;   // generic kernel handles it

    // ---- stage 0: channel-summed image tile, halo 4 (predicated) ----
    const size_t plane = (size_t)H * W;
    for (int i = tid; i < IW_W * IW_H; i += NTHREADS) {
        int r = i / IW_W, c = i % IW_W;
        int gy = y0 - 4 + r, gx = x0 - 4 + c;
        float v = 0.f;
        if (gy >= 0 && gy < H && gx >= 0 && gx < W) {
            size_t base = (size_t)b * C * plane + (size_t)gy * W + gx;
            if (C == 3) {
                float v0 = __ldg(&img[base]);
                float v1 = __ldg(&img[base + plane]);
                float v2 = __ldg(&img[base + 2 * plane]);
                v = v0 + v1 + v2;
            } else {
                for (int ch = 0; ch < C; ch++) v += __ldg(&img[base + (size_t)ch * plane]);
            }
        }
        simg[i] = v;
    }
    __syncthreads();

    // ---- stage 1: gaussian blur (strips of 2): 35 x 38 = 1330 units ----
    for (int u = tid; u < 35 * BW_H; u += NTHREADS) {
        int row = u / 35, cs = (u % 35) * 2;
        float a[3][4];
        #pragma unroll
        for (int dr = 0; dr < 3; dr++)
            #pragma unroll
            for (int dc = 0; dc < 4; dc++)
                a[dr][dc] = simg[(row + dr) * IW_W + cs + dc];
        float o0 = 0.f, o1 = 0.f;
        #pragma unroll
        for (int dr = 0; dr < 3; dr++)
            #pragma unroll
            for (int dc = 0; dc < 3; dc++) {
                float w = kgf[dr * 3 + dc];
                o0 = fmaf(w, a[dr][dc],     o0);
                o1 = fmaf(w, a[dr][dc + 1], o1);
            }
        {
            int gy = y0 - 3 + row, gx = x0 - 3 + cs;
            bool iny = (gy >= 0 && gy < H);
            if (!(iny && gx     >= 0 && gx     < W)) o0 = 0.f;
            if (!(iny && gx + 1 >= 0 && gx + 1 < W)) o1 = 0.f;
        }
        sblur[row * BW_W + cs]     = o0;
        sblur[row * BW_W + cs + 1] = o1;
    }
    __syncthreads();

    // ---- stage 2: sobel + magnitude (strips of 4): 17 x 36 = 612 units ----
    for (int u = tid; u < 17 * MW_H; u += NTHREADS) {
        int row = u / 17, cs = (u % 17) * 4;
        float bv[3][6];
        #pragma unroll
        for (int dr = 0; dr < 3; dr++)
            #pragma unroll
            for (int dc = 0; dc < 6; dc++)
                bv[dr][dc] = sblur[(row + dr) * BW_W + cs + dc];
        #pragma unroll
        for (int k = 0; k < 4; k++) {
            float ax = 0.f, ay = 0.f;
            #pragma unroll
            for (int dr = 0; dr < 3; dr++)
                #pragma unroll
                for (int dc = 0; dc < 3; dc++) {
                    float t = bv[dr][dc + k];
                    ax = fmaf(ksxf[dr * 3 + dc], t, ax);
                    ay = fmaf(ksyf[dr * 3 + dc], t, ay);
                }
            ax *= invC; ay *= invC;
            float m = sqrtf(ax * ax + ay * ay);
            {
                int gy = y0 - 2 + row, gx = x0 - 2 + cs + k;
                if (!(gy >= 0 && gy < H && gx >= 0 && gx < W)) m = 0.f;
            }
            smag[row * MW_W + cs + k] = m;
        }
    }
    __syncthreads();

    // ---- stage 3: S = conv(mag, ksum) (strips of 2): 33 x 34 = 1122 units --
    for (int u = tid; u < 33 * SW_H; u += NTHREADS) {
        int row = u / 33, cs = (u % 33) * 2;
        float m[3][4];
        #pragma unroll
        for (int dr = 0; dr < 3; dr++)
            #pragma unroll
            for (int dc = 0; dc < 4; dc++)
                m[dr][dc] = smag[(row + dr) * MW_W + cs + dc];
        float s0 = 0.f, s1 = 0.f;
        #pragma unroll
        for (int dr = 0; dr < 3; dr++)
            #pragma unroll
            for (int dc = 0; dc < 3; dc++) {
                float w = ksum[dr * 3 + dc];
                s0 = fmaf(w, m[dr][dc],     s0);
                s1 = fmaf(w, m[dr][dc + 1], s1);
            }
        {
            int gy = y0 - 1 + row, gx = x0 - 1 + cs;
            bool iny = (gy >= 0 && gy < H);
            if (!(iny && gx     >= 0 && gx     < W)) s0 = 0.f;
            if (!(iny && gx + 1 >= 0 && gx + 1 < W)) s1 = 0.f;
        }
        sS[row * SW_W + cs]     = s0;
        sS[row * SW_W + cs + 1] = s1;
    }
    __syncthreads();

    // ---- stage 4: 8-neighbor sum of S; exactly 512 units; float4 store ----
    {
        int row = tid / 16, cs = (tid % 16) * 4;
        float s[3][6];
        #pragma unroll
        for (int dr = 0; dr < 3; dr++)
            #pragma unroll
            for (int dc = 0; dc < 6; dc++)
                s[dr][dc] = sS[(row + dr) * SW_W + cs + dc];
        float o[4];
        #pragma unroll
        for (int k = 0; k < 4; k++) {
            float acc = 0.f;
            #pragma unroll
            for (int dr = 0; dr < 3; dr++)
                #pragma unroll
                for (int dc = 0; dc < 3; dc++) {
                    if (dr == 1 && dc == 1) continue;   // exclude center exactly
                    acc += s[dr][dc + k];
                }
            o[k] = acc;
        }
        size_t oidx = ((size_t)b * H + (y0 + row)) * W + x0 + cs;
        *reinterpret_cast<float4*>(&out[oidx]) = make_float4(o[0], o[1], o[2], o[3]);
    }
}

// ===========================================================================
// GENERIC kernel: exact fallback for arbitrary weights. Early-exits when the
// fast kernel's validity conditions held (fast kernel already wrote output).
// ===========================================================================
__global__ __launch_bounds__(NTHREADS, 2)
void canny_generic_kernel(const float* __restrict__ img,
                          const float* __restrict__ gauss_w,
                          const float* __restrict__ sobel_x_w,
                          const float* __restrict__ sobel_y_w,
                          const float* __restrict__ dir_w,
                          const float* __restrict__ nms_w,
                          float* __restrict__ out,
                          int B, int C, int H, int W)
{
    __shared__ float simg [IW_W * IW_H];
    __shared__ float sblur[BW_W * BW_H];
    __shared__ float sgx  [MW_W * MW_H];
    __shared__ float sgy  [MW_W * MW_H];
    __shared__ float kcomp[81];
    __shared__ int   sbad;

    const int tid = threadIdx.x;
    const int b   = blockIdx.z;
    const int x0  = blockIdx.x * TDX;
    const int y0  = blockIdx.y * TDY;
    const float invC = 1.0f / (float)C;

    if (tid == 0) sbad = 0;
    __syncthreads();

    // Same validity conditions as the fast kernel; if they hold, exit.
    for (int i = tid; i < 27 * (C - 1); i += NTHREADS) {
        int ch = 1 + i / 27, j = i % 27, arr = j / 9, t = j % 9;
        const float* base = (arr == 0) ? gauss_w : (arr == 1) ? sobel_x_w : sobel_y_w;
        if (__float_as_uint(__ldg(&base[ch * 9 + t])) != __float_as_uint(__ldg(&base[t])))
            atomicOr(&sbad, 1);
    }
    if (tid < 8) {
        float n0 = __ldg(&nms_w[tid * 9]);
        #pragma unroll
        for (int off = 0; off < 9; off++) {
            float nv = __ldg(&nms_w[tid * 9 + off]);
            if (off == 4) { if (nv != 0.f) atomicOr(&sbad, 1); }
            else          { if (__float_as_uint(nv) != __float_as_uint(n0)) atomicOr(&sbad, 1); }
        }
    }
    __syncthreads();
    if (!sbad) return;   // fast kernel handled it

    if (tid < 81) {
        int off = tid / 9, t = tid % 9;
        float acc = 0.f;
        #pragma unroll
        for (int d = 0; d < 8; d++)
            acc = fmaf(__ldg(&nms_w[d * 9 + off]), __ldg(&dir_w[d * 9 + t]), acc);
        kcomp[tid] = acc;
    }
    for (int i = tid; i < MW_W * MW_H; i += NTHREADS) { sgx[i] = 0.f; sgy[i] = 0.f; }
    __syncthreads();

    for (int ch = 0; ch < C; ch++) {
        for (int i = tid; i < IW_W * IW_H; i += NTHREADS) {
            int r = i / IW_W, c = i % IW_W;
            int gy = y0 - 4 + r, gx = x0 - 4 + c;
            float v = 0.f;
            if (gy >= 0 && gy < H && gx >= 0 && gx < W)
                v = img[(((size_t)b * C + ch) * H + gy) * W + gx];
            simg[i] = v;
        }
        float wg[9], wx[9], wy[9];
        #pragma unroll
        for (int t = 0; t < 9; t++) {
            wg[t] = __ldg(&gauss_w  [ch * 9 + t]);
            wx[t] = __ldg(&sobel_x_w[ch * 9 + t]);
            wy[t] = __ldg(&sobel_y_w[ch * 9 + t]);
        }
        __syncthreads();
        for (int i = tid; i < BW_W * BW_H; i += NTHREADS) {
            int row = i / BW_W, c = i % BW_W;
            int gy = y0 - 3 + row, gx = x0 - 3 + c;
            float v = 0.f;
            if (gy >= 0 && gy < H && gx >= 0 && gx < W) {
                #pragma unroll
                for (int dr = 0; dr < 3; dr++)
                    #pragma unroll
                    for (int dc = 0; dc < 3; dc++)
                        v = fmaf(wg[dr * 3 + dc], simg[(row + dr) * IW_W + c + dc], v);
            }
            sblur[i] = v;
        }
        __syncthreads();
        for (int i = tid; i < MW_W * MW_H; i += NTHREADS) {
            int row = i / MW_W, c = i % MW_W;
            float ax = 0.f, ay = 0.f;
            #pragma unroll
            for (int dr = 0; dr < 3; dr++)
                #pragma unroll
                for (int dc = 0; dc < 3; dc++) {
                    float t = sblur[(row + dr) * BW_W + c + dc];
                    ax = fmaf(wx[dr * 3 + dc], t, ax);
                    ay = fmaf(wy[dr * 3 + dc], t, ay);
                }
            sgx[i] += ax;
            sgy[i] += ay;
        }
        __syncthreads();
    }
    for (int i = tid; i < MW_W * MW_H; i += NTHREADS) {
        int row = i / MW_W, c = i % MW_W;
        int gy = y0 - 2 + row, gx = x0 - 2 + c;
        float m = 0.f;
        if (gy >= 0 && gy < H && gx >= 0 && gx < W) {
            float gxx = sgx[i] * invC, gyy = sgy[i] * invC;
            m = sqrtf(gxx * gxx + gyy * gyy);
        }
        sgx[i] = m;
    }
    __syncthreads();
    for (int i = tid; i < TDX * TDY; i += NTHREADS) {
        int r = i / TDX, c = i % TDX;
        int y = y0 + r, x = x0 + c;
        float acc = 0.f;
        #pragma unroll
        for (int oi = 0; oi < 3; oi++)
            #pragma unroll
            for (int oj = 0; oj < 3; oj++) {
                int p = y + oi - 1, q = x + oj - 1;
                if (p < 0 || p >= H || q < 0 || q >= W) continue;
                float s = 0.f;
                #pragma unroll
                for (int dr = 0; dr < 3; dr++)
                    #pragma unroll
                    for (int dc = 0; dc < 3; dc++)
                        s = fmaf(kcomp[(oi * 3 + oj) * 9 + dr * 3 + dc],
                                 sgx[(r + oi + dr) * MW_W + c + oj + dc], s);
                acc += s;
            }
        out[((size_t)b * H + y) * W + x] = acc;
    }
}

extern "C" void kernel_launch(void* const* d_in, const int* in_sizes, int n_in,
                              void* d_out, int out_size)
{
    const float* img       = (const float*)d_in[0];
    const float* gauss_w   = (const float*)d_in[1];
    const float* sobel_x_w = (const float*)d_in[2];
    const float* sobel_y_w = (const float*)d_in[3];
    const float* dir_w     = (const float*)d_in[4];
    const float* nms_w     = (const float*)d_in[5];
    float* out = (float*)d_out;

    const int H = 512, W = 512;
    const int C = in_sizes[1] / 9;                 // (C,1,3,3) -> C
    const int B = in_sizes[0] / (C * H * W);

    dim3 grid(W / TDX, H / TDY, B);                // 8 x 16 x B
    canny_fast_kernel<<<grid, NTHREADS>>>(img, gauss_w, sobel_x_w, sobel_y_w,
                                          dir_w, nms_w, out, B, C, H, W);
    canny_generic_kernel<<<grid, NTHREADS>>>(img, gauss_w, sobel_x_w, sobel_y_w,
                                             dir_w, nms_w, out, B, C, H, W);
}